// round 1
// baseline (speedup 1.0000x reference)
#include <cuda_runtime.h>
#include <cstdint>

#define MARGIN 0.5f
#define EPSV   1e-5f

#define N_MAX  8192
#define BM 64
#define BN 64
#define BK 32

// Scratch accumulators (allocation-free rule: __device__ globals)
__device__ float g_pos[N_MAX];
__device__ float g_neg[N_MAX];
__device__ int   g_is64;

// ---------------------------------------------------------------------------
// Zero the row accumulators (graph replays must start clean every time)
// ---------------------------------------------------------------------------
__global__ void zero_kernel(int n) {
    int i = blockIdx.x * blockDim.x + threadIdx.x;
    if (i < n) { g_pos[i] = 0.0f; g_neg[i] = 0.0f; }
}

// ---------------------------------------------------------------------------
// Probe whether target is serialized as int64 or int32.
// int64 layout: every 8-byte word holds a small class id (0..99).
// int32 layout: 8-byte word = lo | hi<<32 with hi a random class id ->
// value >= 2^32 unless hi==0 (1% per word). 32 words all small => int64
// with false-positive probability ~1e-64.
// ---------------------------------------------------------------------------
__global__ void probe_kernel(const void* targ, int n) {
    const long long* t = (const long long*)targ;
    int m = n / 2; if (m > 33) m = 33;
    bool is64 = true;
    for (int i = 1; i < m; ++i) {
        long long v = t[i];
        if (v < 0 || v >= (1LL << 30)) { is64 = false; break; }
    }
    g_is64 = is64 ? 1 : 0;
}

// ---------------------------------------------------------------------------
// Fused sim-tile GEMM + masked row reductions.
// Tile (row_tile, col_tile) computes sim[rowbase:+64, colbase:+64] and
// accumulates:
//   neg[gi] += sim         where t[gi]!=t[gj] && sim>MARGIN   (all launched tiles)
//   pos[gi] += (1-sim)     where t[gi]==t[gj] && sim<1-EPS    (only new-row x new-col tiles)
// Tiles with rowbase>=n_new && colbase>=n_new are never needed (early exit).
// ---------------------------------------------------------------------------
__global__ __launch_bounds__(256, 2)
void sim_kernel(const float* __restrict__ feat, const void* __restrict__ targ,
                int n, int d, int n_new)
{
    const int rowbase = blockIdx.y * BM;
    const int colbase = blockIdx.x * BN;
    if (rowbase >= n_new && colbase >= n_new) return;   // unused quadrant

    __shared__ float As[BK][BM + 1];
    __shared__ float Bs[BK][BN + 1];
    __shared__ int   trow_s[BM];
    __shared__ int   tcol_s[BN];

    const int tid = threadIdx.x;        // 0..255
    const int tx  = tid & 15;           // 0..15  (column group)
    const int ty  = tid >> 4;           // 0..15  (row group)

    // Load targets for this tile (uniform branch on serialized width)
    const int is64 = g_is64;
    if (tid < BM) {
        int v = is64 ? (int)((const long long*)targ)[rowbase + tid]
                     : ((const int*)targ)[rowbase + tid];
        trow_s[tid] = v;
    } else if (tid < BM + BN) {
        int j = tid - BM;
        int v = is64 ? (int)((const long long*)targ)[colbase + j]
                     : ((const int*)targ)[colbase + j];
        tcol_s[j] = v;
    }

    float acc[4][4] = {};

    const float4* f4 = reinterpret_cast<const float4*>(feat);
    const int d4 = d >> 2;              // row stride in float4 (64)

    for (int k0 = 0; k0 < d; k0 += BK) {
        // 64 rows x 32 k = 512 float4 loads per operand; 256 threads x 2 each
        #pragma unroll
        for (int it = 0; it < 2; ++it) {
            int idx = tid + it * 256;       // 0..511
            int r = idx >> 3;               // row within tile
            int q = idx & 7;                // which float4 in the 32-wide k slab
            float4 va = __ldg(&f4[(size_t)(rowbase + r) * d4 + (k0 >> 2) + q]);
            As[q * 4 + 0][r] = va.x; As[q * 4 + 1][r] = va.y;
            As[q * 4 + 2][r] = va.z; As[q * 4 + 3][r] = va.w;
            float4 vb = __ldg(&f4[(size_t)(colbase + r) * d4 + (k0 >> 2) + q]);
            Bs[q * 4 + 0][r] = vb.x; Bs[q * 4 + 1][r] = vb.y;
            Bs[q * 4 + 2][r] = vb.z; Bs[q * 4 + 3][r] = vb.w;
        }
        __syncthreads();

        #pragma unroll
        for (int k = 0; k < BK; ++k) {
            float a[4], b[4];
            #pragma unroll
            for (int i = 0; i < 4; ++i) a[i] = As[k][ty * 4 + i];
            #pragma unroll
            for (int j = 0; j < 4; ++j) b[j] = Bs[k][tx * 4 + j];
            #pragma unroll
            for (int i = 0; i < 4; ++i)
                #pragma unroll
                for (int j = 0; j < 4; ++j)
                    acc[i][j] = fmaf(a[i], b[j], acc[i][j]);
        }
        __syncthreads();
    }

    // Epilogue: mask + per-row reduction across the 16 column-group threads.
    const bool do_pos = (colbase < n_new) && (rowbase < n_new);

    #pragma unroll
    for (int i = 0; i < 4; ++i) {
        const int lrow = ty * 4 + i;
        const int ti   = trow_s[lrow];
        float p = 0.0f, ng = 0.0f;
        #pragma unroll
        for (int j = 0; j < 4; ++j) {
            float s  = acc[i][j];
            int   tj = tcol_s[tx * 4 + j];
            if (ti != tj) {
                if (s > MARGIN) ng += s;
            } else if (do_pos && s < 1.0f - EPSV) {
                p += 1.0f - s;
            }
        }
        // Reduce over the 16 lanes sharing this row (tx = 0..15, aligned
        // 16-lane groups within the warp: xor offsets 8,4,2,1 stay in-group)
        #pragma unroll
        for (int off = 8; off > 0; off >>= 1) {
            p  += __shfl_xor_sync(0xffffffffu, p,  off);
            ng += __shfl_xor_sync(0xffffffffu, ng, off);
        }
        if (tx == 0) {
            int gi = rowbase + lrow;
            atomicAdd(&g_neg[gi], ng);
            if (do_pos) atomicAdd(&g_pos[gi], p);
        }
    }
}

// ---------------------------------------------------------------------------
// Final scalar: mean_i( alpha*pos'[i] + (1-alpha)*neg[i] ),
// pos'[i] = pos[i] for i<n_new else pos[n_new-1] (stale).
// ---------------------------------------------------------------------------
__global__ void finish_kernel(float* out, int n, int n_new, float alpha) {
    __shared__ double sh[256];
    const double a  = (double)alpha;
    const double b  = 1.0 - a;
    const double stale = (double)g_pos[n_new - 1];
    double s = 0.0;
    for (int i = threadIdx.x; i < n; i += 256) {
        double pv = (i < n_new) ? (double)g_pos[i] : stale;
        s += a * pv + b * (double)g_neg[i];
    }
    sh[threadIdx.x] = s;
    __syncthreads();
    for (int off = 128; off > 0; off >>= 1) {
        if (threadIdx.x < off) sh[threadIdx.x] += sh[threadIdx.x + off];
        __syncthreads();
    }
    if (threadIdx.x == 0) out[0] = (float)(sh[0] / (double)n);
}

// ---------------------------------------------------------------------------
extern "C" void kernel_launch(void* const* d_in, const int* in_sizes, int n_in,
                              void* d_out, int out_size)
{
    const float* feat = (const float*)d_in[0];
    const void*  targ = d_in[1];

    const int n     = in_sizes[1];             // 8192
    const int d     = in_sizes[0] / n;         // 256
    const int n_new = in_sizes[2];             // 4096
    const int n_old = (n_in > 3) ? in_sizes[3] : 0;
    const float alpha = (n_old != 0) ? 0.9f : 0.5f;

    zero_kernel<<<(n + 255) / 256, 256>>>(n);
    probe_kernel<<<1, 1>>>(targ, n);

    dim3 grid(n / BN, n / BM);
    sim_kernel<<<grid, 256>>>(feat, targ, n, d, n_new);

    finish_kernel<<<1, 256>>>((float*)d_out, n, n_new, alpha);
}

// round 3
// speedup vs baseline: 4.7737x; 4.7737x over previous
#include <cuda_runtime.h>
#include <cuda_bf16.h>
#include <cstdint>

#define MARGIN 0.5f
#define EPSV   1e-5f

#define N_MAX  8192
#define D_MAX  256
#define TM 128
#define TN 128

// tcgen05 is an sm_103a arch-specific ('a') feature. The harness also runs a
// plain compute_103/sm_103 ptxas pass, so every tcgen05 instruction must be
// compiled ONLY under the arch-feature macro.
#if defined(__CUDA_ARCH__) && (__CUDA_ARCH__ == 1030) && defined(__CUDA_ARCH_FEAT_SM103_ALL)
#define HAS_TCGEN05 1
#else
#define HAS_TCGEN05 0
#endif

// ---------------------------------------------------------------------------
// Device scratch (allocation-free rule: __device__ globals)
// ---------------------------------------------------------------------------
__device__ float          g_pos[N_MAX];
__device__ float          g_neg[N_MAX];
__device__ int            g_targ[N_MAX];
__device__ __nv_bfloat16  g_featbf[N_MAX * D_MAX];
__device__ int            g_is64;
__device__ int            g_has_tc;

// ---------------------------------------------------------------------------
// One-time prep kernels
// ---------------------------------------------------------------------------
__global__ void zero_kernel(int n) {
    int i = blockIdx.x * blockDim.x + threadIdx.x;
    if (i < n) { g_pos[i] = 0.0f; g_neg[i] = 0.0f; }
}

// Which cubin is loaded? Only the sm_103a pass sets the flag.
__global__ void detect_kernel() {
#if HAS_TCGEN05
    g_has_tc = 1;
#else
    g_has_tc = 0;
#endif
}

// int64-vs-int32 serialization probe for target: 32 consecutive 8-byte words
// all in [0, 2^30) => int64 layout (false-positive prob ~1e-64).
__global__ void probe_kernel(const void* targ, int n) {
    const long long* t = (const long long*)targ;
    int m = n / 2; if (m > 33) m = 33;
    bool is64 = true;
    for (int i = 1; i < m; ++i) {
        long long v = t[i];
        if (v < 0 || v >= (1LL << 30)) { is64 = false; break; }
    }
    g_is64 = is64 ? 1 : 0;
}

// fp32 feature -> bf16 (row-major), target -> int32
__global__ void convert_kernel(const float* __restrict__ feat,
                               const void* __restrict__ targ, int n, int d) {
    int i = blockIdx.x * blockDim.x + threadIdx.x;
    int total4 = (n * d) >> 2;
    if (i < total4) {
        float4 v = reinterpret_cast<const float4*>(feat)[i];
        __nv_bfloat162 lo = __nv_bfloat162(__float2bfloat16(v.x), __float2bfloat16(v.y));
        __nv_bfloat162 hi = __nv_bfloat162(__float2bfloat16(v.z), __float2bfloat16(v.w));
        reinterpret_cast<__nv_bfloat162*>(g_featbf)[i * 2 + 0] = lo;
        reinterpret_cast<__nv_bfloat162*>(g_featbf)[i * 2 + 1] = hi;
    }
    if (i < n) {
        g_targ[i] = g_is64 ? (int)((const long long*)targ)[i]
                           : ((const int*)targ)[i];
    }
}

// ---------------------------------------------------------------------------
// PTX helpers (used only inside HAS_TCGEN05 sections)
// ---------------------------------------------------------------------------
__device__ __forceinline__ uint32_t smem_u32(const void* p) {
    uint32_t a;
    asm("{ .reg .u64 t; cvta.to.shared.u64 t, %1; cvt.u32.u64 %0, t; }"
        : "=r"(a) : "l"(p));
    return a;
}

__device__ __forceinline__ uint32_t elect_one() {
    uint32_t pred;
    asm volatile("{\n\t.reg .pred p;\n\telect.sync _|p, 0xFFFFFFFF;\n\t"
                 "selp.b32 %0, 1, 0, p;\n\t}" : "=r"(pred));
    return pred;
}

#define MBARRIER_INIT(mbar, count) \
    asm volatile("mbarrier.init.shared.b64 [%0], %1;" \
                 :: "r"((uint32_t)(mbar)), "r"((uint32_t)(count)) : "memory")

#define MBARRIER_WAIT_PARITY(mbar, parity) do {                                   \
    uint32_t _m = (uint32_t)(mbar); uint32_t _p = (uint32_t)(parity);             \
    uint32_t _done;                                                               \
    asm volatile("{\n\t.reg .pred p;\n\t"                                         \
        "mbarrier.try_wait.parity.acquire.cta.shared::cta.b64 p, [%1], %2;\n\t"   \
        "selp.b32 %0, 1, 0, p;\n\t}" : "=r"(_done) : "r"(_m), "r"(_p) : "memory");\
    if (!_done) {                                                                 \
        asm volatile("{\n\t.reg .pred P1;\n\t"                                    \
            "WAIT_LOOP_%=:\n\t"                                                   \
            "mbarrier.try_wait.parity.acquire.cta.shared::cta.b64 P1, [%0], %1, 0x989680;\n\t" \
            "@P1 bra.uni WAIT_DONE_%=;\n\t"                                       \
            "bra.uni WAIT_LOOP_%=;\n\t"                                           \
            "WAIT_DONE_%=:\n\t}" :: "r"(_m), "r"(_p) : "memory");                 \
    }                                                                             \
} while (0)

#if HAS_TCGEN05

#define TCGEN05_ALLOC(smem_result_addr, nCols) \
    asm volatile("tcgen05.alloc.cta_group::1.sync.aligned.shared::cta.b32 [%0], %1;" \
                 :: "r"((uint32_t)(smem_result_addr)), "r"((uint32_t)(nCols)) : "memory")

#define TCGEN05_DEALLOC(tmem_addr, nCols) \
    asm volatile("tcgen05.dealloc.cta_group::1.sync.aligned.b32 %0, %1;" \
                 :: "r"(tmem_addr), "r"((uint32_t)(nCols)))

#define TCGEN05_RELINQUISH() \
    asm volatile("tcgen05.relinquish_alloc_permit.cta_group::1.sync.aligned;")

#define TCGEN05_COMMIT(mbar) \
    asm volatile("tcgen05.commit.cta_group::1.mbarrier::arrive::one.shared::cluster.b64 [%0];" \
                 :: "r"((uint32_t)(mbar)) : "memory")

#define TCGEN05_FENCE_AFTER()  asm volatile("tcgen05.fence::after_thread_sync;"  ::: "memory")
#define TCGEN05_FENCE_BEFORE() asm volatile("tcgen05.fence::before_thread_sync;" ::: "memory")
#define TCGEN05_WAIT_LD()      asm volatile("tcgen05.wait::ld.sync.aligned;"     ::: "memory")

#define TCGEN05_LD_32X32B_X32(r, tmem_addr) \
    asm volatile( \
        "tcgen05.ld.sync.aligned.32x32b.x32.b32 " \
        "{%0, %1, %2, %3, %4, %5, %6, %7, " \
        " %8, %9, %10, %11, %12, %13, %14, %15, " \
        " %16, %17, %18, %19, %20, %21, %22, %23, " \
        " %24, %25, %26, %27, %28, %29, %30, %31}, [%32];" \
        : "=r"((r)[0]),  "=r"((r)[1]),  "=r"((r)[2]),  "=r"((r)[3]), \
          "=r"((r)[4]),  "=r"((r)[5]),  "=r"((r)[6]),  "=r"((r)[7]), \
          "=r"((r)[8]),  "=r"((r)[9]),  "=r"((r)[10]), "=r"((r)[11]), \
          "=r"((r)[12]), "=r"((r)[13]), "=r"((r)[14]), "=r"((r)[15]), \
          "=r"((r)[16]), "=r"((r)[17]), "=r"((r)[18]), "=r"((r)[19]), \
          "=r"((r)[20]), "=r"((r)[21]), "=r"((r)[22]), "=r"((r)[23]), \
          "=r"((r)[24]), "=r"((r)[25]), "=r"((r)[26]), "=r"((r)[27]), \
          "=r"((r)[28]), "=r"((r)[29]), "=r"((r)[30]), "=r"((r)[31]) \
        : "r"(tmem_addr))

// 64-bit SMEM descriptor: SW128 K-major, version=1, SBO=64, LBO=1
static constexpr uint64_t SMEM_DESC_BASE_SW128 =
    (uint64_t(2)  << 61) | (uint64_t(1) << 46) | (uint64_t(64) << 32) | (uint64_t(1) << 16);

__device__ __forceinline__ uint64_t make_desc(uint32_t addr) {
    return SMEM_DESC_BASE_SW128 | ((uint64_t)(addr >> 4) & 0x3FFF);
}

// SS-mode bf16 MMA, cta_group::1
__device__ __forceinline__ void mma_f16_ss(uint32_t d_tmem, uint64_t a_desc,
                                           uint64_t b_desc, uint32_t idesc, bool acc) {
    uint32_t en = acc ? 1u : 0u;
    asm volatile(
        "{\n\t.reg .pred p;\n\tsetp.ne.u32 p, %5, 0;\n\t"
        "tcgen05.mma.cta_group::1.kind::f16 [%0], %1, %2, %3, {%4, %4, %4, %4}, p;\n\t}"
        :: "r"(d_tmem), "l"(a_desc), "l"(b_desc), "r"(idesc), "r"(0u), "r"(en)
        : "memory");
}

// idesc: fp32 acc, bf16 a/b, M=128 (8<<24), N=128 (16<<17)
static constexpr uint32_t MMA_IDESC =
    (1u << 4) | (1u << 7) | (1u << 10) | ((TN / 8) << 17) | ((TM / 16) << 24);

#endif  // HAS_TCGEN05

// ---------------------------------------------------------------------------
// SMEM layout for the tcgen05 kernel
// ---------------------------------------------------------------------------
#define SMEM_A        0
#define SMEM_B        65536
#define SMEM_TCOL     131072
#define SMEM_MBAR     131584
#define SMEM_TMEMPTR  131592
#define SMEM_TOTAL    131616

#define TMEM_COLS     128

// ---------------------------------------------------------------------------
// tcgen05 path: fused 128x128 sim tile + masked epilogue
// ---------------------------------------------------------------------------
__global__ __launch_bounds__(256, 1)
void sim_tc_kernel(int n, int d, int n_new)
{
#if HAS_TCGEN05
    const int rowbase = blockIdx.y * TM;
    const int colbase = blockIdx.x * TN;
    if (rowbase >= n_new && colbase >= n_new) return;   // unused quadrant

    extern __shared__ __align__(1024) char smem[];
    const uint32_t smem_base = smem_u32(smem);
    const int tid  = threadIdx.x;
    const int wid  = tid >> 5;
    const int lane = tid & 31;

    if (wid == 0) {
        TCGEN05_ALLOC(smem_base + SMEM_TMEMPTR, TMEM_COLS);
        TCGEN05_RELINQUISH();
    }
    if (tid == 0) MBARRIER_INIT(smem_base + SMEM_MBAR, 1);

    int* tcol_s = reinterpret_cast<int*>(smem + SMEM_TCOL);
    if (tid < TN) tcol_s[tid] = g_targ[colbase + tid];

    // Load A/B bf16 tiles into SW128 K-major blocked-atom layout.
    // atom = 8 rows x 128B; 16 atom-rows; atom-col stride 16KB.
    {
        const uint4* src = reinterpret_cast<const uint4*>(g_featbf);
        const int d8 = d >> 3;                 // 16B chunks per row (32)
        const int chunks = TM * d8;            // 4096
        for (int idx = tid; idx < chunks; idx += 256) {
            int r  = idx / d8;
            int ch = idx - r * d8;
            uint32_t byte = ((uint32_t)((r >> 3) + (ch >> 3) * 16) << 10)
                          + ((uint32_t)(r & 7) << 7) + ((uint32_t)(ch & 7) << 4);
            uint32_t sw = byte ^ ((byte >> 3) & 0x70);
            uint4 va = src[(size_t)(rowbase + r) * d8 + ch];
            *reinterpret_cast<uint4*>(smem + SMEM_A + sw) = va;
            uint4 vb = src[(size_t)(colbase + r) * d8 + ch];
            *reinterpret_cast<uint4*>(smem + SMEM_B + sw) = vb;
        }
    }

    asm volatile("fence.proxy.async.shared::cta;" ::: "memory");
    __syncthreads();

    uint32_t tmem_base;
    asm volatile("ld.shared.b32 %0, [%1];" : "=r"(tmem_base)
                 : "r"(smem_base + SMEM_TMEMPTR));

    if (wid == 0) {
        if (elect_one()) {
            uint64_t a_base = make_desc(smem_base + SMEM_A);
            uint64_t b_base = make_desc(smem_base + SMEM_B);
            const int nk = d >> 4;             // 16 K-steps of K=16
            for (int s = 0; s < nk; ++s) {
                uint64_t off = ((uint64_t)(s >> 2) << 10) | (uint64_t)((s & 3) << 1);
                mma_f16_ss(tmem_base, a_base + off, b_base + off, MMA_IDESC, s > 0);
            }
            TCGEN05_COMMIT(smem_base + SMEM_MBAR);
        }
    }

    MBARRIER_WAIT_PARITY(smem_base + SMEM_MBAR, 0);
    TCGEN05_FENCE_AFTER();

    // Epilogue: warp w -> rows (w&3)*32+lane, cols (w>>2)*64 .. +63
    {
        const int colh = wid >> 2;
        const int row  = (wid & 3) * 32 + lane;
        const int grow = rowbase + row;
        const int ti   = g_targ[grow];

        float p = 0.0f, ng = 0.0f;
        uint32_t dr[32];
        #pragma unroll
        for (int half = 0; half < 2; ++half) {
            TCGEN05_LD_32X32B_X32(dr, tmem_base + colh * 64 + half * 32);
            TCGEN05_WAIT_LD();
            #pragma unroll
            for (int c = 0; c < 32; ++c) {
                const int lc = colh * 64 + half * 32 + c;
                const float s = __uint_as_float(dr[c]);
                const int tj = tcol_s[lc];
                if (ti != tj) {
                    if (s > MARGIN) ng += s;
                } else if ((colbase + lc) < n_new && s < 1.0f - EPSV) {
                    p += 1.0f - s;
                }
            }
        }
        TCGEN05_FENCE_BEFORE();

        atomicAdd(&g_neg[grow], ng);
        if (p != 0.0f) atomicAdd(&g_pos[grow], p);
    }

    __syncthreads();
    if (wid == 0) TCGEN05_DEALLOC(tmem_base, TMEM_COLS);
#endif  // HAS_TCGEN05
}

// ---------------------------------------------------------------------------
// FFMA fallback (R1 kernel, 823us) — runs only if tcgen05 cubin not loaded
// ---------------------------------------------------------------------------
#define BM 64
#define BN 64
#define BK 32

__global__ __launch_bounds__(256, 2)
void sim_ffma_kernel(const float* __restrict__ feat, const void* __restrict__ targ,
                     int n, int d, int n_new)
{
    if (g_has_tc) return;                               // tc path already did it

    const int rowbase = blockIdx.y * BM;
    const int colbase = blockIdx.x * BN;
    if (rowbase >= n_new && colbase >= n_new) return;

    __shared__ float As[BK][BM + 1];
    __shared__ float Bs[BK][BN + 1];
    __shared__ int   trow_s[BM];
    __shared__ int   tcol_s[BN];

    const int tid = threadIdx.x;
    const int tx  = tid & 15;
    const int ty  = tid >> 4;

    const int is64 = g_is64;
    if (tid < BM) {
        trow_s[tid] = is64 ? (int)((const long long*)targ)[rowbase + tid]
                           : ((const int*)targ)[rowbase + tid];
    } else if (tid < BM + BN) {
        int j = tid - BM;
        tcol_s[j] = is64 ? (int)((const long long*)targ)[colbase + j]
                         : ((const int*)targ)[colbase + j];
    }

    float acc[4][4] = {};
    const float4* f4 = reinterpret_cast<const float4*>(feat);
    const int d4 = d >> 2;

    for (int k0 = 0; k0 < d; k0 += BK) {
        #pragma unroll
        for (int it = 0; it < 2; ++it) {
            int idx = tid + it * 256;
            int r = idx >> 3;
            int q = idx & 7;
            float4 va = __ldg(&f4[(size_t)(rowbase + r) * d4 + (k0 >> 2) + q]);
            As[q * 4 + 0][r] = va.x; As[q * 4 + 1][r] = va.y;
            As[q * 4 + 2][r] = va.z; As[q * 4 + 3][r] = va.w;
            float4 vb = __ldg(&f4[(size_t)(colbase + r) * d4 + (k0 >> 2) + q]);
            Bs[q * 4 + 0][r] = vb.x; Bs[q * 4 + 1][r] = vb.y;
            Bs[q * 4 + 2][r] = vb.z; Bs[q * 4 + 3][r] = vb.w;
        }
        __syncthreads();
        #pragma unroll
        for (int k = 0; k < BK; ++k) {
            float a[4], b[4];
            #pragma unroll
            for (int i = 0; i < 4; ++i) a[i] = As[k][ty * 4 + i];
            #pragma unroll
            for (int j = 0; j < 4; ++j) b[j] = Bs[k][tx * 4 + j];
            #pragma unroll
            for (int i = 0; i < 4; ++i)
                #pragma unroll
                for (int j = 0; j < 4; ++j)
                    acc[i][j] = fmaf(a[i], b[j], acc[i][j]);
        }
        __syncthreads();
    }

    const bool do_pos = (colbase < n_new) && (rowbase < n_new);
    #pragma unroll
    for (int i = 0; i < 4; ++i) {
        const int lrow = ty * 4 + i;
        const int ti   = trow_s[lrow];
        float p = 0.0f, ng = 0.0f;
        #pragma unroll
        for (int j = 0; j < 4; ++j) {
            float s  = acc[i][j];
            int   tj = tcol_s[tx * 4 + j];
            if (ti != tj) {
                if (s > MARGIN) ng += s;
            } else if (do_pos && s < 1.0f - EPSV) {
                p += 1.0f - s;
            }
        }
        #pragma unroll
        for (int off = 8; off > 0; off >>= 1) {
            p  += __shfl_xor_sync(0xffffffffu, p,  off);
            ng += __shfl_xor_sync(0xffffffffu, ng, off);
        }
        if (tx == 0) {
            int gi = rowbase + lrow;
            atomicAdd(&g_neg[gi], ng);
            if (do_pos) atomicAdd(&g_pos[gi], p);
        }
    }
}

// ---------------------------------------------------------------------------
// Final scalar: mean_i( alpha*pos'[i] + (1-alpha)*neg[i] )
// ---------------------------------------------------------------------------
__global__ void finish_kernel(float* out, int n, int n_new, float alpha) {
    __shared__ double sh[256];
    const double a = (double)alpha;
    const double b = 1.0 - a;
    const double stale = (double)g_pos[n_new - 1];
    double s = 0.0;
    for (int i = threadIdx.x; i < n; i += 256) {
        double pv = (i < n_new) ? (double)g_pos[i] : stale;
        s += a * pv + b * (double)g_neg[i];
    }
    sh[threadIdx.x] = s;
    __syncthreads();
    for (int off = 128; off > 0; off >>= 1) {
        if (threadIdx.x < off) sh[threadIdx.x] += sh[threadIdx.x + off];
        __syncthreads();
    }
    if (threadIdx.x == 0) out[0] = (float)(sh[0] / (double)n);
}

// ---------------------------------------------------------------------------
extern "C" void kernel_launch(void* const* d_in, const int* in_sizes, int n_in,
                              void* d_out, int out_size)
{
    const float* feat = (const float*)d_in[0];
    const void*  targ = d_in[1];

    const int n     = in_sizes[1];             // 8192
    const int d     = in_sizes[0] / n;         // 256
    const int n_new = in_sizes[2];             // 4096
    const int n_old = (n_in > 3) ? in_sizes[3] : 0;
    const float alpha = (n_old != 0) ? 0.9f : 0.5f;

    cudaFuncSetAttribute(sim_tc_kernel,
                         cudaFuncAttributeMaxDynamicSharedMemorySize, SMEM_TOTAL);

    zero_kernel<<<(n + 255) / 256, 256>>>(n);
    detect_kernel<<<1, 1>>>();
    probe_kernel<<<1, 1>>>(targ, n);
    {
        int total4 = (n * d) >> 2;
        convert_kernel<<<(total4 + 255) / 256, 256>>>(feat, targ, n, d);
    }

    dim3 grid_tc(n / TN, n / TM);
    sim_tc_kernel<<<grid_tc, 256, SMEM_TOTAL>>>(n, d, n_new);

    dim3 grid_ff(n / BN, n / BM);
    sim_ffma_kernel<<<grid_ff, 256>>>(feat, targ, n, d, n_new);

    finish_kernel<<<1, 256>>>((float*)d_out, n, n_new, alpha);
}

// round 4
// speedup vs baseline: 9.4910x; 1.9882x over previous
#include <cuda_runtime.h>
#include <cuda_bf16.h>
#include <cstdint>

#define MARGIN 0.5f
#define EPSV   1e-5f

#define N_MAX  8192
#define D_MAX  256
#define TM 128
#define TN 128

// tcgen05 is an sm_103a arch-specific feature; the harness also compiles a
// plain compute_103 pass, so guard every tcgen05 instruction.
#if defined(__CUDA_ARCH__) && (__CUDA_ARCH__ == 1030) && defined(__CUDA_ARCH_FEAT_SM103_ALL)
#define HAS_TCGEN05 1
#else
#define HAS_TCGEN05 0
#endif

// ---------------------------------------------------------------------------
// Device scratch
// ---------------------------------------------------------------------------
__device__ float          g_pos[N_MAX];
__device__ float          g_neg[N_MAX];
__device__ int            g_targ[N_MAX];
__device__ __nv_bfloat16  g_featbf[N_MAX * D_MAX];
__device__ int            g_is64;
__device__ int            g_done;

// ---------------------------------------------------------------------------
// Prep kernels
// ---------------------------------------------------------------------------
// int64-vs-int32 serialization probe for target (32 small 8-byte words => i64)
__global__ void probe_kernel(const void* targ, int n) {
    const long long* t = (const long long*)targ;
    int m = n / 2; if (m > 33) m = 33;
    bool is64 = true;
    for (int i = 1; i < m; ++i) {
        long long v = t[i];
        if (v < 0 || v >= (1LL << 30)) { is64 = false; break; }
    }
    g_is64 = is64 ? 1 : 0;
}

// fp32->bf16 features, target->int32, zero accumulators + ticket
__global__ void convert_kernel(const float* __restrict__ feat,
                               const void* __restrict__ targ, int n, int d) {
    int i = blockIdx.x * blockDim.x + threadIdx.x;
    int total4 = (n * d) >> 2;
    if (i < total4) {
        float4 v = reinterpret_cast<const float4*>(feat)[i];
        __nv_bfloat162 lo = __nv_bfloat162(__float2bfloat16(v.x), __float2bfloat16(v.y));
        __nv_bfloat162 hi = __nv_bfloat162(__float2bfloat16(v.z), __float2bfloat16(v.w));
        reinterpret_cast<__nv_bfloat162*>(g_featbf)[i * 2 + 0] = lo;
        reinterpret_cast<__nv_bfloat162*>(g_featbf)[i * 2 + 1] = hi;
    }
    if (i < n) {
        g_pos[i] = 0.0f; g_neg[i] = 0.0f;
        g_targ[i] = g_is64 ? (int)((const long long*)targ)[i]
                           : ((const int*)targ)[i];
    }
    if (i == 0) g_done = 0;
}

// ---------------------------------------------------------------------------
// PTX helpers
// ---------------------------------------------------------------------------
__device__ __forceinline__ uint32_t smem_u32(const void* p) {
    uint32_t a;
    asm("{ .reg .u64 t; cvta.to.shared.u64 t, %1; cvt.u32.u64 %0, t; }"
        : "=r"(a) : "l"(p));
    return a;
}

__device__ __forceinline__ uint32_t elect_one() {
    uint32_t pred;
    asm volatile("{\n\t.reg .pred p;\n\telect.sync _|p, 0xFFFFFFFF;\n\t"
                 "selp.b32 %0, 1, 0, p;\n\t}" : "=r"(pred));
    return pred;
}

#define MBARRIER_INIT(mbar, count) \
    asm volatile("mbarrier.init.shared.b64 [%0], %1;" \
                 :: "r"((uint32_t)(mbar)), "r"((uint32_t)(count)) : "memory")

#define MBARRIER_WAIT_PARITY(mbar, parity) do {                                   \
    uint32_t _m = (uint32_t)(mbar); uint32_t _p = (uint32_t)(parity);             \
    uint32_t _done;                                                               \
    asm volatile("{\n\t.reg .pred p;\n\t"                                         \
        "mbarrier.try_wait.parity.acquire.cta.shared::cta.b64 p, [%1], %2;\n\t"   \
        "selp.b32 %0, 1, 0, p;\n\t}" : "=r"(_done) : "r"(_m), "r"(_p) : "memory");\
    if (!_done) {                                                                 \
        asm volatile("{\n\t.reg .pred P1;\n\t"                                    \
            "WAIT_LOOP_%=:\n\t"                                                   \
            "mbarrier.try_wait.parity.acquire.cta.shared::cta.b64 P1, [%0], %1, 0x989680;\n\t" \
            "@P1 bra.uni WAIT_DONE_%=;\n\t"                                       \
            "bra.uni WAIT_LOOP_%=;\n\t"                                           \
            "WAIT_DONE_%=:\n\t}" :: "r"(_m), "r"(_p) : "memory");                 \
    }                                                                             \
} while (0)

#if HAS_TCGEN05

#define TCGEN05_ALLOC(sm_addr, nCols) \
    asm volatile("tcgen05.alloc.cta_group::1.sync.aligned.shared::cta.b32 [%0], %1;" \
                 :: "r"((uint32_t)(sm_addr)), "r"((uint32_t)(nCols)) : "memory")
#define TCGEN05_DEALLOC(tmem_addr, nCols) \
    asm volatile("tcgen05.dealloc.cta_group::1.sync.aligned.b32 %0, %1;" \
                 :: "r"(tmem_addr), "r"((uint32_t)(nCols)))
#define TCGEN05_RELINQUISH() \
    asm volatile("tcgen05.relinquish_alloc_permit.cta_group::1.sync.aligned;")
#define TCGEN05_COMMIT(mbar) \
    asm volatile("tcgen05.commit.cta_group::1.mbarrier::arrive::one.shared::cluster.b64 [%0];" \
                 :: "r"((uint32_t)(mbar)) : "memory")
#define TCGEN05_FENCE_AFTER()  asm volatile("tcgen05.fence::after_thread_sync;"  ::: "memory")
#define TCGEN05_FENCE_BEFORE() asm volatile("tcgen05.fence::before_thread_sync;" ::: "memory")
#define TCGEN05_WAIT_LD()      asm volatile("tcgen05.wait::ld.sync.aligned;"     ::: "memory")

#define TCGEN05_LD_32X32B_X32(r, tmem_addr) \
    asm volatile( \
        "tcgen05.ld.sync.aligned.32x32b.x32.b32 " \
        "{%0, %1, %2, %3, %4, %5, %6, %7, " \
        " %8, %9, %10, %11, %12, %13, %14, %15, " \
        " %16, %17, %18, %19, %20, %21, %22, %23, " \
        " %24, %25, %26, %27, %28, %29, %30, %31}, [%32];" \
        : "=r"((r)[0]),  "=r"((r)[1]),  "=r"((r)[2]),  "=r"((r)[3]), \
          "=r"((r)[4]),  "=r"((r)[5]),  "=r"((r)[6]),  "=r"((r)[7]), \
          "=r"((r)[8]),  "=r"((r)[9]),  "=r"((r)[10]), "=r"((r)[11]), \
          "=r"((r)[12]), "=r"((r)[13]), "=r"((r)[14]), "=r"((r)[15]), \
          "=r"((r)[16]), "=r"((r)[17]), "=r"((r)[18]), "=r"((r)[19]), \
          "=r"((r)[20]), "=r"((r)[21]), "=r"((r)[22]), "=r"((r)[23]), \
          "=r"((r)[24]), "=r"((r)[25]), "=r"((r)[26]), "=r"((r)[27]), \
          "=r"((r)[28]), "=r"((r)[29]), "=r"((r)[30]), "=r"((r)[31]) \
        : "r"(tmem_addr))

// SW128 K-major descriptor: version=1, SBO=64, LBO=1
static constexpr uint64_t SMEM_DESC_BASE_SW128 =
    (uint64_t(2)  << 61) | (uint64_t(1) << 46) | (uint64_t(64) << 32) | (uint64_t(1) << 16);

__device__ __forceinline__ uint64_t make_desc(uint32_t addr) {
    return SMEM_DESC_BASE_SW128 | ((uint64_t)(addr >> 4) & 0x3FFF);
}

__device__ __forceinline__ void mma_f16_ss(uint32_t d_tmem, uint64_t a_desc,
                                           uint64_t b_desc, uint32_t idesc, bool acc) {
    uint32_t en = acc ? 1u : 0u;
    asm volatile(
        "{\n\t.reg .pred p;\n\tsetp.ne.u32 p, %5, 0;\n\t"
        "tcgen05.mma.cta_group::1.kind::f16 [%0], %1, %2, %3, {%4, %4, %4, %4}, p;\n\t}"
        :: "r"(d_tmem), "l"(a_desc), "l"(b_desc), "r"(idesc), "r"(0u), "r"(en)
        : "memory");
}

// fp32 acc, bf16 a/b, M=128, N=128
static constexpr uint32_t MMA_IDESC =
    (1u << 4) | (1u << 7) | (1u << 10) | ((TN / 8) << 17) | ((TM / 16) << 24);

#endif  // HAS_TCGEN05

// ---------------------------------------------------------------------------
// SMEM layout
// ---------------------------------------------------------------------------
#define SMEM_A        0
#define SMEM_B0       65536
#define SMEM_B1       131072
#define SMEM_TCOL0    196608
#define SMEM_TCOL1    197120
#define SMEM_MBAR0    197632
#define SMEM_MBAR1    197640
#define SMEM_TMEMPTR  197648
#define SMEM_TOTAL    197664

#define TMEM_COLS     256   // two 128-col fp32 D buffers

#define GRID_CTAS     148

// ---------------------------------------------------------------------------
// Persistent pipelined sim kernel (+ folded final reduction)
// ---------------------------------------------------------------------------
#if HAS_TCGEN05
// Load one 128-row bf16 tile (rows gbase..gbase+127, all d cols) into SW128
// K-major blocked-atom layout at smem byte offset `dst`.
__device__ __forceinline__ void load_tile(char* smem, uint32_t dst,
                                          int gbase, int d8, int tid) {
    const uint4* src = reinterpret_cast<const uint4*>(g_featbf);
    if (d8 == 32) {
        #pragma unroll
        for (int k = 0; k < 16; ++k) {
            int idx = tid + k * 256;
            int r = idx >> 5, ch = idx & 31;
            uint32_t byte = ((uint32_t)((r >> 3) + (ch >> 3) * 16) << 10)
                          + ((uint32_t)(r & 7) << 7) + ((uint32_t)(ch & 7) << 4);
            uint32_t sw = byte ^ ((byte >> 3) & 0x70);
            *reinterpret_cast<uint4*>(smem + dst + sw) =
                src[(size_t)(gbase + r) * 32 + ch];
        }
    } else {
        int chunks = TM * d8;
        for (int idx = tid; idx < chunks; idx += 256) {
            int r = idx / d8, ch = idx - r * d8;
            uint32_t byte = ((uint32_t)((r >> 3) + (ch >> 3) * 16) << 10)
                          + ((uint32_t)(r & 7) << 7) + ((uint32_t)(ch & 7) << 4);
            uint32_t sw = byte ^ ((byte >> 3) & 0x70);
            *reinterpret_cast<uint4*>(smem + dst + sw) =
                src[(size_t)(gbase + r) * (size_t)d8 + ch];
        }
    }
}

__device__ __forceinline__ void issue_mma_batch(uint32_t d_tmem, uint32_t a_addr,
                                                uint32_t b_addr, int nk,
                                                uint32_t mbar) {
    uint64_t a_base = make_desc(a_addr);
    uint64_t b_base = make_desc(b_addr);
    for (int s = 0; s < nk; ++s) {
        // desc offset (16B units): atom-col stride 1024 units, K=16 step 2 units
        uint64_t off = ((uint64_t)(s >> 2) << 10) | (uint64_t)((s & 3) << 1);
        mma_f16_ss(d_tmem, a_base + off, b_base + off, MMA_IDESC, s > 0);
    }
    TCGEN05_COMMIT(mbar);
}
#endif

__global__ __launch_bounds__(256, 1)
void sim_tc_kernel(float* out, int n, int d, int n_new, float alpha)
{
#if HAS_TCGEN05
    extern __shared__ __align__(1024) char smem[];
    const uint32_t sb   = smem_u32(smem);
    const int tid  = threadIdx.x;
    const int wid  = tid >> 5;
    const int lane = tid & 31;

    if (wid == 0) {
        TCGEN05_ALLOC(sb + SMEM_TMEMPTR, TMEM_COLS);
        TCGEN05_RELINQUISH();
    }
    if (tid == 0) {
        MBARRIER_INIT(sb + SMEM_MBAR0, 1);
        MBARRIER_INIT(sb + SMEM_MBAR1, 1);
    }
    __syncthreads();

    uint32_t tmem;
    asm volatile("ld.shared.b32 %0, [%1];" : "=r"(tmem) : "r"(sb + SMEM_TMEMPTR));

    // ---- tile enumeration -------------------------------------------------
    const int slabs_new = n_new / TM;            // 32
    const int cols_full = n / TN;                // 64
    const int cols_new  = n_new / TN;            // 32
    const int slabs_tot = n / TM;                // 64
    const int tiles_new = slabs_new * cols_full; // 2048
    const int tiles_tot = tiles_new + (slabs_tot - slabs_new) * cols_new; // 3072

    const int G = gridDim.x;
    int t   = (int)((long long)blockIdx.x       * tiles_tot / G);
    int end = (int)((long long)(blockIdx.x + 1) * tiles_tot / G);

    const int d8 = d >> 3;
    const int nk = d >> 4;
    const int row  = (wid & 3) * 32 + lane;      // row within slab
    const int colh = wid >> 2;                   // column half (0/1)

    int c = 0;                                   // pipeline tile counter

    while (t < end) {
        // decode run: contiguous tiles sharing a row slab
        int slab, col0, slab_cols, slab_t0;
        if (t < tiles_new) {
            slab = t / cols_full; col0 = t - slab * cols_full;
            slab_cols = cols_full; slab_t0 = slab * cols_full;
        } else {
            int u = t - tiles_new;
            slab = slabs_new + u / cols_new; col0 = u % cols_new;
            slab_cols = cols_new;
            slab_t0 = tiles_new + (slab - slabs_new) * cols_new;
        }
        int run_len = slab_t0 + slab_cols - t;
        if (run_len > end - t) run_len = end - t;
        const int rowbase = slab * TM;
        const bool row_new = rowbase < n_new;

        // ---- run prologue: A + first B + first tcol, issue MMA(0) ---------
        load_tile(smem, SMEM_A, rowbase, d8, tid);
        {
            int colbase = col0 * TN;
            load_tile(smem, (c & 1) ? SMEM_B1 : SMEM_B0, colbase, d8, tid);
            if (tid < TN)
                ((int*)(smem + ((c & 1) ? SMEM_TCOL1 : SMEM_TCOL0)))[tid] =
                    g_targ[colbase + tid];
        }
        asm volatile("fence.proxy.async.shared::cta;" ::: "memory");
        __syncthreads();
        if (wid == 0 && elect_one()) {
            issue_mma_batch(tmem + (c & 1) * 128, sb + SMEM_A,
                            sb + ((c & 1) ? SMEM_B1 : SMEM_B0), nk,
                            sb + ((c & 1) ? SMEM_MBAR1 : SMEM_MBAR0));
        }

        const int ti = __ldg(&g_targ[rowbase + row]);
        float p = 0.0f, ng = 0.0f;

        // ---- pipelined loop ------------------------------------------------
        for (int i = 0; i < run_len; ++i) {
            const int cc = c + i;
            if (i + 1 < run_len) {
                int colbase = (col0 + i + 1) * TN;
                load_tile(smem, ((cc + 1) & 1) ? SMEM_B1 : SMEM_B0,
                          colbase, d8, tid);
                if (tid < TN)
                    ((int*)(smem + (((cc + 1) & 1) ? SMEM_TCOL1 : SMEM_TCOL0)))[tid] =
                        g_targ[colbase + tid];
            }
            asm volatile("fence.proxy.async.shared::cta;" ::: "memory");
            __syncthreads();

            MBARRIER_WAIT_PARITY(sb + ((cc & 1) ? SMEM_MBAR1 : SMEM_MBAR0),
                                 (cc >> 1) & 1);
            TCGEN05_FENCE_AFTER();

            if (i + 1 < run_len && wid == 0 && elect_one()) {
                issue_mma_batch(tmem + ((cc + 1) & 1) * 128, sb + SMEM_A,
                                sb + (((cc + 1) & 1) ? SMEM_B1 : SMEM_B0), nk,
                                sb + (((cc + 1) & 1) ? SMEM_MBAR1 : SMEM_MBAR0));
            }

            // epilogue(t): masks + accumulate (overlaps MMA(t+1))
            {
                const int colbase = (col0 + i) * TN;
                const bool do_pos = row_new && (colbase < n_new);
                const int* tc = (const int*)(smem + ((cc & 1) ? SMEM_TCOL1
                                                              : SMEM_TCOL0));
                uint32_t dr[32];
                #pragma unroll
                for (int half = 0; half < 2; ++half) {
                    TCGEN05_LD_32X32B_X32(dr, tmem + (cc & 1) * 128
                                              + colh * 64 + half * 32);
                    TCGEN05_WAIT_LD();
                    #pragma unroll
                    for (int j = 0; j < 32; ++j) {
                        const int lc = colh * 64 + half * 32 + j;
                        const float s = __uint_as_float(dr[j]);
                        const int tj = tc[lc];
                        if (ti != tj) {
                            if (s > MARGIN) ng += s;
                        } else if (do_pos && s < 1.0f - EPSV) {
                            p += 1.0f - s;
                        }
                    }
                }
                TCGEN05_FENCE_BEFORE();
            }
            __syncthreads();
        }

        // ---- run epilogue: flush accumulators (2 threads per row) ---------
        atomicAdd(&g_neg[rowbase + row], ng);
        if (p != 0.0f) atomicAdd(&g_pos[rowbase + row], p);

        c += run_len;
        t += run_len;
    }

    __syncthreads();
    if (wid == 0) TCGEN05_DEALLOC(tmem, TMEM_COLS);

    // ---- last CTA computes the final scalar --------------------------------
    __threadfence();
    __shared__ int s_last;
    if (tid == 0)
        s_last = (atomicAdd(&g_done, 1) == gridDim.x - 1) ? 1 : 0;
    __syncthreads();
    if (s_last) {
        double* sh = reinterpret_cast<double*>(smem);   // reuse A region
        const double a = (double)alpha;
        const double b = 1.0 - a;
        const double stale = (double)__ldcg(&g_pos[n_new - 1]);
        double s = 0.0;
        for (int i = tid; i < n; i += 256) {
            double pv = (i < n_new) ? (double)__ldcg(&g_pos[i]) : stale;
            s += a * pv + b * (double)__ldcg(&g_neg[i]);
        }
        sh[tid] = s;
        __syncthreads();
        for (int off = 128; off > 0; off >>= 1) {
            if (tid < off) sh[tid] += sh[tid + off];
            __syncthreads();
        }
        if (tid == 0) out[0] = (float)(sh[0] / (double)n);
    }
#endif  // HAS_TCGEN05
}

// ---------------------------------------------------------------------------
extern "C" void kernel_launch(void* const* d_in, const int* in_sizes, int n_in,
                              void* d_out, int out_size)
{
    const float* feat = (const float*)d_in[0];
    const void*  targ = d_in[1];

    const int n     = in_sizes[1];             // 8192
    const int d     = in_sizes[0] / n;         // 256
    const int n_new = in_sizes[2];             // 4096
    const int n_old = (n_in > 3) ? in_sizes[3] : 0;
    const float alpha = (n_old != 0) ? 0.9f : 0.5f;

    cudaFuncSetAttribute(sim_tc_kernel,
                         cudaFuncAttributeMaxDynamicSharedMemorySize, SMEM_TOTAL);

    probe_kernel<<<1, 1>>>(targ, n);
    {
        int total4 = (n * d) >> 2;
        convert_kernel<<<(total4 + 255) / 256, 256>>>(feat, targ, n, d);
    }
    sim_tc_kernel<<<GRID_CTAS, 256, SMEM_TOTAL>>>((float*)d_out, n, d, n_new, alpha);
}

// round 5
// speedup vs baseline: 13.2972x; 1.4010x over previous
#include <cuda_runtime.h>
#include <cuda_bf16.h>
#include <cstdint>

#define MARGIN 0.5f
#define EPSV   1e-5f

#define N_MAX  8192
#define D_MAX  256
#define TM 128
#define TN 128

#if defined(__CUDA_ARCH__) && (__CUDA_ARCH__ == 1030) && defined(__CUDA_ARCH_FEAT_SM103_ALL)
#define HAS_TCGEN05 1
#else
#define HAS_TCGEN05 0
#endif

// ---------------------------------------------------------------------------
// Device scratch
// ---------------------------------------------------------------------------
__device__ float          g_pos[N_MAX];
__device__ float          g_neg[N_MAX];
__device__ int            g_targ[N_MAX];
__device__ __nv_bfloat16  g_featbf[N_MAX * D_MAX];
__device__ int            g_done;

// ---------------------------------------------------------------------------
// Prep: fp32->bf16 features, target->int32 (with inline int64/int32 probe),
// zero accumulators + ticket.
// ---------------------------------------------------------------------------
__global__ void convert_kernel(const float* __restrict__ feat,
                               const void* __restrict__ targ, int n, int d) {
    __shared__ int s_is64;
    const int i = blockIdx.x * blockDim.x + threadIdx.x;

    // blocks that handle targets probe the serialization width once
    const bool need_t = (blockIdx.x * blockDim.x) < n;
    if (need_t) {
        if (threadIdx.x == 0) {
            const long long* t = (const long long*)targ;
            int m = n / 2; if (m > 33) m = 33;
            bool is64 = true;
            for (int k = 1; k < m; ++k) {
                long long v = t[k];
                if (v < 0 || v >= (1LL << 30)) { is64 = false; break; }
            }
            s_is64 = is64 ? 1 : 0;
        }
        __syncthreads();
    }

    const int total4 = (n * d) >> 2;
    if (i < total4) {
        float4 v = reinterpret_cast<const float4*>(feat)[i];
        __nv_bfloat162 lo = __nv_bfloat162(__float2bfloat16(v.x), __float2bfloat16(v.y));
        __nv_bfloat162 hi = __nv_bfloat162(__float2bfloat16(v.z), __float2bfloat16(v.w));
        reinterpret_cast<__nv_bfloat162*>(g_featbf)[i * 2 + 0] = lo;
        reinterpret_cast<__nv_bfloat162*>(g_featbf)[i * 2 + 1] = hi;
    }
    if (i < n) {
        g_pos[i] = 0.0f; g_neg[i] = 0.0f;
        g_targ[i] = s_is64 ? (int)((const long long*)targ)[i]
                           : ((const int*)targ)[i];
    }
    if (i == 0) g_done = 0;
}

// ---------------------------------------------------------------------------
// PTX helpers
// ---------------------------------------------------------------------------
__device__ __forceinline__ uint32_t smem_u32(const void* p) {
    uint32_t a;
    asm("{ .reg .u64 t; cvta.to.shared.u64 t, %1; cvt.u32.u64 %0, t; }"
        : "=r"(a) : "l"(p));
    return a;
}

__device__ __forceinline__ uint32_t elect_one() {
    uint32_t pred;
    asm volatile("{\n\t.reg .pred p;\n\telect.sync _|p, 0xFFFFFFFF;\n\t"
                 "selp.b32 %0, 1, 0, p;\n\t}" : "=r"(pred));
    return pred;
}

#define MBARRIER_INIT(mbar, count) \
    asm volatile("mbarrier.init.shared.b64 [%0], %1;" \
                 :: "r"((uint32_t)(mbar)), "r"((uint32_t)(count)) : "memory")

#define MBARRIER_WAIT_PARITY(mbar, parity) do {                                   \
    uint32_t _m = (uint32_t)(mbar); uint32_t _p = (uint32_t)(parity);             \
    uint32_t _done;                                                               \
    asm volatile("{\n\t.reg .pred p;\n\t"                                         \
        "mbarrier.try_wait.parity.acquire.cta.shared::cta.b64 p, [%1], %2;\n\t"   \
        "selp.b32 %0, 1, 0, p;\n\t}" : "=r"(_done) : "r"(_m), "r"(_p) : "memory");\
    if (!_done) {                                                                 \
        asm volatile("{\n\t.reg .pred P1;\n\t"                                    \
            "WAIT_LOOP_%=:\n\t"                                                   \
            "mbarrier.try_wait.parity.acquire.cta.shared::cta.b64 P1, [%0], %1, 0x989680;\n\t" \
            "@P1 bra.uni WAIT_DONE_%=;\n\t"                                       \
            "bra.uni WAIT_LOOP_%=;\n\t"                                           \
            "WAIT_DONE_%=:\n\t}" :: "r"(_m), "r"(_p) : "memory");                 \
    }                                                                             \
} while (0)

#if HAS_TCGEN05

#define TCGEN05_ALLOC(sm_addr, nCols) \
    asm volatile("tcgen05.alloc.cta_group::1.sync.aligned.shared::cta.b32 [%0], %1;" \
                 :: "r"((uint32_t)(sm_addr)), "r"((uint32_t)(nCols)) : "memory")
#define TCGEN05_DEALLOC(tmem_addr, nCols) \
    asm volatile("tcgen05.dealloc.cta_group::1.sync.aligned.b32 %0, %1;" \
                 :: "r"(tmem_addr), "r"((uint32_t)(nCols)))
#define TCGEN05_RELINQUISH() \
    asm volatile("tcgen05.relinquish_alloc_permit.cta_group::1.sync.aligned;")
#define TCGEN05_COMMIT(mbar) \
    asm volatile("tcgen05.commit.cta_group::1.mbarrier::arrive::one.shared::cluster.b64 [%0];" \
                 :: "r"((uint32_t)(mbar)) : "memory")
#define TCGEN05_FENCE_AFTER()  asm volatile("tcgen05.fence::after_thread_sync;"  ::: "memory")
#define TCGEN05_FENCE_BEFORE() asm volatile("tcgen05.fence::before_thread_sync;" ::: "memory")
#define TCGEN05_WAIT_LD()      asm volatile("tcgen05.wait::ld.sync.aligned;"     ::: "memory")

#define TCGEN05_LD_32X32B_X32(r, tmem_addr) \
    asm volatile( \
        "tcgen05.ld.sync.aligned.32x32b.x32.b32 " \
        "{%0, %1, %2, %3, %4, %5, %6, %7, " \
        " %8, %9, %10, %11, %12, %13, %14, %15, " \
        " %16, %17, %18, %19, %20, %21, %22, %23, " \
        " %24, %25, %26, %27, %28, %29, %30, %31}, [%32];" \
        : "=r"((r)[0]),  "=r"((r)[1]),  "=r"((r)[2]),  "=r"((r)[3]), \
          "=r"((r)[4]),  "=r"((r)[5]),  "=r"((r)[6]),  "=r"((r)[7]), \
          "=r"((r)[8]),  "=r"((r)[9]),  "=r"((r)[10]), "=r"((r)[11]), \
          "=r"((r)[12]), "=r"((r)[13]), "=r"((r)[14]), "=r"((r)[15]), \
          "=r"((r)[16]), "=r"((r)[17]), "=r"((r)[18]), "=r"((r)[19]), \
          "=r"((r)[20]), "=r"((r)[21]), "=r"((r)[22]), "=r"((r)[23]), \
          "=r"((r)[24]), "=r"((r)[25]), "=r"((r)[26]), "=r"((r)[27]), \
          "=r"((r)[28]), "=r"((r)[29]), "=r"((r)[30]), "=r"((r)[31]) \
        : "r"(tmem_addr))

// SW128 K-major descriptor: version=1, SBO=64, LBO=1
static constexpr uint64_t SMEM_DESC_BASE_SW128 =
    (uint64_t(2)  << 61) | (uint64_t(1) << 46) | (uint64_t(64) << 32) | (uint64_t(1) << 16);

__device__ __forceinline__ uint64_t make_desc(uint32_t addr) {
    return SMEM_DESC_BASE_SW128 | ((uint64_t)(addr >> 4) & 0x3FFF);
}

__device__ __forceinline__ void mma_f16_ss(uint32_t d_tmem, uint64_t a_desc,
                                           uint64_t b_desc, uint32_t idesc, bool acc) {
    uint32_t en = acc ? 1u : 0u;
    asm volatile(
        "{\n\t.reg .pred p;\n\tsetp.ne.u32 p, %5, 0;\n\t"
        "tcgen05.mma.cta_group::1.kind::f16 [%0], %1, %2, %3, {%4, %4, %4, %4}, p;\n\t}"
        :: "r"(d_tmem), "l"(a_desc), "l"(b_desc), "r"(idesc), "r"(0u), "r"(en)
        : "memory");
}

// fp32 acc, bf16 a/b, M=128, N=128
static constexpr uint32_t MMA_IDESC =
    (1u << 4) | (1u << 7) | (1u << 10) | ((TN / 8) << 17) | ((TM / 16) << 24);

#endif  // HAS_TCGEN05

// ---------------------------------------------------------------------------
// SMEM layout
// ---------------------------------------------------------------------------
#define SMEM_A        0
#define SMEM_B0       65536
#define SMEM_B1       131072
#define SMEM_TCOL0    196608
#define SMEM_TCOL1    197120
#define SMEM_MBAR0    197632
#define SMEM_MBAR1    197640
#define SMEM_TMEMPTR  197648
#define SMEM_TOTAL    197664

#define TMEM_COLS     256   // two 128-col fp32 D buffers

#define GRID_CTAS     148

#if HAS_TCGEN05
// Load one 128-row bf16 tile into SW128 K-major blocked-atom layout at `dst`.
// NT = number of cooperating threads (tid in [0, NT)).
template <int NT>
__device__ __forceinline__ void load_tile(char* smem, uint32_t dst,
                                          int gbase, int d8, int tid) {
    const uint4* src = reinterpret_cast<const uint4*>(g_featbf);
    if (d8 == 32) {
        #pragma unroll
        for (int k = 0; k < 4096 / NT; ++k) {
            int idx = tid + k * NT;
            int r = idx >> 5, ch = idx & 31;
            uint32_t byte = ((uint32_t)((r >> 3) + (ch >> 3) * 16) << 10)
                          + ((uint32_t)(r & 7) << 7) + ((uint32_t)(ch & 7) << 4);
            uint32_t sw = byte ^ ((byte >> 3) & 0x70);
            *reinterpret_cast<uint4*>(smem + dst + sw) =
                src[(size_t)(gbase + r) * 32 + ch];
        }
    } else {
        int chunks = TM * d8;
        for (int idx = tid; idx < chunks; idx += NT) {
            int r = idx / d8, ch = idx - r * d8;
            uint32_t byte = ((uint32_t)((r >> 3) + (ch >> 3) * 16) << 10)
                          + ((uint32_t)(r & 7) << 7) + ((uint32_t)(ch & 7) << 4);
            uint32_t sw = byte ^ ((byte >> 3) & 0x70);
            *reinterpret_cast<uint4*>(smem + dst + sw) =
                src[(size_t)(gbase + r) * (size_t)d8 + ch];
        }
    }
}

__device__ __forceinline__ void issue_mma_batch(uint32_t d_tmem, uint32_t a_addr,
                                                uint32_t b_addr, int nk,
                                                uint32_t mbar) {
    uint64_t a_base = make_desc(a_addr);
    uint64_t b_base = make_desc(b_addr);
    for (int s = 0; s < nk; ++s) {
        uint64_t off = ((uint64_t)(s >> 2) << 10) | (uint64_t)((s & 3) << 1);
        mma_f16_ss(d_tmem, a_base + off, b_base + off, MMA_IDESC, s > 0);
    }
    TCGEN05_COMMIT(mbar);
}
#endif

// ---------------------------------------------------------------------------
// Persistent warp-specialized sim kernel (+ folded final reduction)
//   warps 0-3: epilogue (wait MMA(t), LDTM, masks, accumulate)
//   warps 4-7: loaders  (B(t+1) + tcol(t+1), overlapping epilogue(t))
// ---------------------------------------------------------------------------
__global__ __launch_bounds__(256, 1)
void sim_tc_kernel(float* out, int n, int d, int n_new, float alpha)
{
#if HAS_TCGEN05
    extern __shared__ __align__(1024) char smem[];
    const uint32_t sb = smem_u32(smem);
    const int tid  = threadIdx.x;
    const int wid  = tid >> 5;
    const int lane = tid & 31;

    if (wid == 0) {
        TCGEN05_ALLOC(sb + SMEM_TMEMPTR, TMEM_COLS);
        TCGEN05_RELINQUISH();
    }
    if (tid == 0) {
        MBARRIER_INIT(sb + SMEM_MBAR0, 1);
        MBARRIER_INIT(sb + SMEM_MBAR1, 1);
    }
    __syncthreads();

    uint32_t tmem;
    asm volatile("ld.shared.b32 %0, [%1];" : "=r"(tmem) : "r"(sb + SMEM_TMEMPTR));

    // ---- tile enumeration ---------------------------------------------------
    const int slabs_new = n_new / TM;
    const int cols_full = n / TN;
    const int cols_new  = n_new / TN;
    const int slabs_tot = n / TM;
    const int tiles_new = slabs_new * cols_full;
    const int tiles_tot = tiles_new + (slabs_tot - slabs_new) * cols_new;

    const int G = gridDim.x;
    int t   = (int)((long long)blockIdx.x       * tiles_tot / G);
    int end = (int)((long long)(blockIdx.x + 1) * tiles_tot / G);

    const int d8 = d >> 3;
    const int nk = d >> 4;
    const bool is_loader = wid >= 4;
    const int  ltid = tid - 128;                // loader-local tid (0..127)
    const int  row  = wid * 32 + lane;          // epilogue row (wid<4: 0..127)

    int c = 0;                                  // global tile counter (parity)

    while (t < end) {
        // decode run: contiguous tiles sharing one row slab
        int slab, col0, slab_cols, slab_t0;
        if (t < tiles_new) {
            slab = t / cols_full; col0 = t - slab * cols_full;
            slab_cols = cols_full; slab_t0 = slab * cols_full;
        } else {
            int u = t - tiles_new;
            slab = slabs_new + u / cols_new; col0 = u % cols_new;
            slab_cols = cols_new;
            slab_t0 = tiles_new + (slab - slabs_new) * cols_new;
        }
        int run_len = slab_t0 + slab_cols - t;
        if (run_len > end - t) run_len = end - t;
        const int rowbase = slab * TM;
        const bool row_new = rowbase < n_new;

        // ---- run prologue (all 256 threads): A + B(0) + tcol(0), MMA(0) ----
        load_tile<256>(smem, SMEM_A, rowbase, d8, tid);
        {
            int colbase = col0 * TN;
            load_tile<256>(smem, (c & 1) ? SMEM_B1 : SMEM_B0, colbase, d8, tid);
            if (tid < TN)
                ((int*)(smem + ((c & 1) ? SMEM_TCOL1 : SMEM_TCOL0)))[tid] =
                    g_targ[colbase + tid];
        }
        asm volatile("fence.proxy.async.shared::cta;" ::: "memory");
        __syncthreads();
        if (wid == 0 && elect_one()) {
            issue_mma_batch(tmem + (c & 1) * 128, sb + SMEM_A,
                            sb + ((c & 1) ? SMEM_B1 : SMEM_B0), nk,
                            sb + ((c & 1) ? SMEM_MBAR1 : SMEM_MBAR0));
        }

        float p = 0.0f, ng = 0.0f;
        int   ti = 0;
        if (!is_loader) ti = __ldg(&g_targ[rowbase + row]);

        // ---- warp-specialized pipelined loop --------------------------------
        for (int i = 0; i < run_len; ++i) {
            const int cc = c + i;

            if (is_loader) {
                // load B(t+1) + tcol(t+1) concurrently with epilogue(t)
                if (i + 1 < run_len) {
                    int colbase = (col0 + i + 1) * TN;
                    load_tile<128>(smem, ((cc + 1) & 1) ? SMEM_B1 : SMEM_B0,
                                   colbase, d8, ltid);
                    if (ltid < TN)
                        ((int*)(smem + (((cc + 1) & 1) ? SMEM_TCOL1
                                                       : SMEM_TCOL0)))[ltid] =
                            g_targ[colbase + ltid];
                    asm volatile("fence.proxy.async.shared::cta;" ::: "memory");
                }
            } else {
                // epilogue(t): wait MMA(t), read D, masks, accumulate
                MBARRIER_WAIT_PARITY(sb + ((cc & 1) ? SMEM_MBAR1 : SMEM_MBAR0),
                                     (cc >> 1) & 1);
                TCGEN05_FENCE_AFTER();

                const int colbase = (col0 + i) * TN;
                const bool do_pos = row_new && (colbase < n_new);
                const int* tc = (const int*)(smem + ((cc & 1) ? SMEM_TCOL1
                                                              : SMEM_TCOL0));
                const uint32_t dbase = tmem + (cc & 1) * 128;
                uint32_t dr[32];
                if (do_pos) {
                    #pragma unroll
                    for (int q = 0; q < 4; ++q) {
                        TCGEN05_LD_32X32B_X32(dr, dbase + q * 32);
                        TCGEN05_WAIT_LD();
                        #pragma unroll
                        for (int j = 0; j < 32; ++j) {
                            const float s = __uint_as_float(dr[j]);
                            const int tj = tc[q * 32 + j];
                            if (ti != tj) {
                                if (s > MARGIN) ng += s;
                            } else if (s < 1.0f - EPSV) {
                                p += 1.0f - s;
                            }
                        }
                    }
                } else {
                    #pragma unroll
                    for (int q = 0; q < 4; ++q) {
                        TCGEN05_LD_32X32B_X32(dr, dbase + q * 32);
                        TCGEN05_WAIT_LD();
                        #pragma unroll
                        for (int j = 0; j < 32; ++j) {
                            const float s = __uint_as_float(dr[j]);
                            if (ti != tc[q * 32 + j] && s > MARGIN) ng += s;
                        }
                    }
                }
                TCGEN05_FENCE_BEFORE();
            }

            __syncthreads();   // B(t+1) visible; D(t) consumed

            if (i + 1 < run_len && wid == 0 && elect_one()) {
                issue_mma_batch(tmem + ((cc + 1) & 1) * 128, sb + SMEM_A,
                                sb + (((cc + 1) & 1) ? SMEM_B1 : SMEM_B0), nk,
                                sb + (((cc + 1) & 1) ? SMEM_MBAR1 : SMEM_MBAR0));
            }
        }

        // ---- run epilogue: flush accumulators (one thread per row) ----------
        if (!is_loader) {
            atomicAdd(&g_neg[rowbase + row], ng);
            if (p != 0.0f) atomicAdd(&g_pos[rowbase + row], p);
        }

        c += run_len;
        t += run_len;
    }

    __syncthreads();
    if (wid == 0) TCGEN05_DEALLOC(tmem, TMEM_COLS);

    // ---- last CTA computes the final scalar ---------------------------------
    __threadfence();
    __shared__ int s_last;
    if (tid == 0)
        s_last = (atomicAdd(&g_done, 1) == gridDim.x - 1) ? 1 : 0;
    __syncthreads();
    if (s_last) {
        double* sh = reinterpret_cast<double*>(smem);
        const double a = (double)alpha;
        const double b = 1.0 - a;
        const double stale = (double)__ldcg(&g_pos[n_new - 1]);
        double s = 0.0;
        for (int i = tid; i < n; i += 256) {
            double pv = (i < n_new) ? (double)__ldcg(&g_pos[i]) : stale;
            s += a * pv + b * (double)__ldcg(&g_neg[i]);
        }
        sh[tid] = s;
        __syncthreads();
        for (int off = 128; off > 0; off >>= 1) {
            if (tid < off) sh[tid] += sh[tid + off];
            __syncthreads();
        }
        if (tid == 0) out[0] = (float)(sh[0] / (double)n);
    }
#endif  // HAS_TCGEN05
}

// ---------------------------------------------------------------------------
extern "C" void kernel_launch(void* const* d_in, const int* in_sizes, int n_in,
                              void* d_out, int out_size)
{
    const float* feat = (const float*)d_in[0];
    const void*  targ = d_in[1];

    const int n     = in_sizes[1];             // 8192
    const int d     = in_sizes[0] / n;         // 256
    const int n_new = in_sizes[2];             // 4096
    const int n_old = (n_in > 3) ? in_sizes[3] : 0;
    const float alpha = (n_old != 0) ? 0.9f : 0.5f;

    cudaFuncSetAttribute(sim_tc_kernel,
                         cudaFuncAttributeMaxDynamicSharedMemorySize, SMEM_TOTAL);

    {
        int total4 = (n * d) >> 2;
        convert_kernel<<<(total4 + 255) / 256, 256>>>(feat, targ, n, d);
    }
    sim_tc_kernel<<<GRID_CTAS, 256, SMEM_TOTAL>>>((float*)d_out, n, d, n_new, alpha);
}